// round 4
// baseline (speedup 1.0000x reference)
#include <cuda_runtime.h>
#include <math.h>
#include <stdint.h>

#define NNODES 50000
#define NEDGES 800000
#define FDIM 128
#define HDIM 128
#define ODIM 128
#define KOBS 4
#define ZDIM 512   /* K*H */
#define MID  256   /* 2*H */

// ---------------- scratch (device globals; no allocation allowed) ----------
__device__ __align__(16) float g_h  [(size_t)NNODES * HDIM];
__device__ __align__(16) float g_hw [(size_t)NNODES * HDIM];
__device__ __align__(16) float g_agg[(size_t)NNODES * ZDIM];
__device__ __align__(16) float g_z1 [(size_t)NNODES * MID];
__device__ double g_colsum  [ZDIM];
__device__ double g_colsumsq[ZDIM];
__device__ float  g_scale[ZDIM];   // bn scale * attention
__device__ float  g_shift[ZDIM];   // bn shift * attention
__device__ unsigned int g_distmax_bits;
// CSR structures
__device__ int g_cnt[NNODES];
__device__ int g_off[NNODES + 1];
__device__ int g_cur[NNODES];
__device__ int g_esrc[NEDGES];
__device__ __align__(16) float4 g_eab[NEDGES];

// ---------------- zero / init ----------------------------------------------
__global__ void k_zero_misc() {
    int i = blockIdx.x * blockDim.x + threadIdx.x;
    if (i == 0) g_distmax_bits = 0u;
    if (i < ZDIM) { g_colsum[i] = 0.0; g_colsumsq[i] = 0.0; }
    for (; i < NNODES; i += gridDim.x * blockDim.x) g_cnt[i] = 0;
}

// ---------------- tf32 tensor-core GEMM ------------------------------------
// C[r,c] = sum_k A[r,k] * W[c,k] + bias[c]       (A @ W^T + b)
// amode==1: A elements transformed on load: relu(a*g_scale[k] + g_shift[k])
__device__ __forceinline__ float to_tf32(float x) {
    float r;
    asm("cvt.rna.tf32.f32 %0, %1;" : "=f"(r) : "f"(x));
    return r;
}

#define ASTRIDE 36   /* pad: bank index = (4*row + k) % 32, conflict-free */

__global__ void __launch_bounds__(256, 2)
k_gemm_tf32(const float* __restrict__ A, const float* __restrict__ W,
            const float* __restrict__ bias, float* __restrict__ C,
            int nrows, int kdim, int mcols, int do_relu, int amode)
{
    __shared__ float As[128][ASTRIDE];
    __shared__ float Ws[128][ASTRIDE];
    const int tid  = threadIdx.x;
    const int warp = tid >> 5;
    const int lane = tid & 31;
    const int row0 = blockIdx.y * 128;
    const int col0 = blockIdx.x * 128;
    const int mw = (warp & 1) * 64;
    const int nw = (warp >> 1) * 32;
    const int gq = lane >> 2;      // group id 0..7
    const int tq = lane & 3;       // thread-in-group 0..3

    float c[4][4][4];
#pragma unroll
    for (int mi = 0; mi < 4; mi++)
#pragma unroll
        for (int ni = 0; ni < 4; ni++)
#pragma unroll
            for (int q = 0; q < 4; q++) c[mi][ni][q] = 0.f;

    for (int k0 = 0; k0 < kdim; k0 += 32) {
#pragma unroll
        for (int t = 0; t < 4; t++) {
            int idx = tid + t * 256;     // 0..1023
            int r   = idx >> 3;          // 0..127
            int kv  = (idx & 7) * 4;     // 0,4,...,28
            float4 v = make_float4(0.f, 0.f, 0.f, 0.f);
            if (row0 + r < nrows)
                v = *(const float4*)&A[(size_t)(row0 + r) * kdim + k0 + kv];
            if (amode) {
                int cc = k0 + kv;
                v.x = fmaxf(fmaf(v.x, g_scale[cc + 0], g_shift[cc + 0]), 0.f);
                v.y = fmaxf(fmaf(v.y, g_scale[cc + 1], g_shift[cc + 1]), 0.f);
                v.z = fmaxf(fmaf(v.z, g_scale[cc + 2], g_shift[cc + 2]), 0.f);
                v.w = fmaxf(fmaf(v.w, g_scale[cc + 3], g_shift[cc + 3]), 0.f);
            }
            As[r][kv + 0] = to_tf32(v.x);
            As[r][kv + 1] = to_tf32(v.y);
            As[r][kv + 2] = to_tf32(v.z);
            As[r][kv + 3] = to_tf32(v.w);
        }
#pragma unroll
        for (int t = 0; t < 4; t++) {
            int idx = tid + t * 256;
            int r   = idx >> 3;
            int kv  = (idx & 7) * 4;
            float4 v = *(const float4*)&W[(size_t)(col0 + r) * kdim + k0 + kv];
            Ws[r][kv + 0] = to_tf32(v.x);
            Ws[r][kv + 1] = to_tf32(v.y);
            Ws[r][kv + 2] = to_tf32(v.z);
            Ws[r][kv + 3] = to_tf32(v.w);
        }
        __syncthreads();

#pragma unroll
        for (int j = 0; j < 4; j++) {
            const int kk = j * 8;
            uint32_t a[4][4], b[4][2];
#pragma unroll
            for (int mi = 0; mi < 4; mi++) {
                int r = mw + mi * 16 + gq;
                a[mi][0] = __float_as_uint(As[r    ][kk + tq]);
                a[mi][1] = __float_as_uint(As[r + 8][kk + tq]);
                a[mi][2] = __float_as_uint(As[r    ][kk + tq + 4]);
                a[mi][3] = __float_as_uint(As[r + 8][kk + tq + 4]);
            }
#pragma unroll
            for (int ni = 0; ni < 4; ni++) {
                int cc = nw + ni * 8 + gq;
                b[ni][0] = __float_as_uint(Ws[cc][kk + tq]);
                b[ni][1] = __float_as_uint(Ws[cc][kk + tq + 4]);
            }
#pragma unroll
            for (int mi = 0; mi < 4; mi++)
#pragma unroll
                for (int ni = 0; ni < 4; ni++) {
                    asm volatile(
                        "mma.sync.aligned.m16n8k8.row.col.f32.tf32.tf32.f32 "
                        "{%0,%1,%2,%3}, {%4,%5,%6,%7}, {%8,%9}, {%0,%1,%2,%3};"
                        : "+f"(c[mi][ni][0]), "+f"(c[mi][ni][1]),
                          "+f"(c[mi][ni][2]), "+f"(c[mi][ni][3])
                        : "r"(a[mi][0]), "r"(a[mi][1]), "r"(a[mi][2]), "r"(a[mi][3]),
                          "r"(b[ni][0]), "r"(b[ni][1]));
                }
        }
        __syncthreads();
    }

#pragma unroll
    for (int mi = 0; mi < 4; mi++) {
        int r0 = row0 + mw + mi * 16 + gq;
#pragma unroll
        for (int ni = 0; ni < 4; ni++) {
            int ccol = col0 + nw + ni * 8 + tq * 2;
            float b0 = bias[ccol], b1 = bias[ccol + 1];
            float v0 = c[mi][ni][0] + b0;
            float v1 = c[mi][ni][1] + b1;
            float v2 = c[mi][ni][2] + b0;
            float v3 = c[mi][ni][3] + b1;
            if (do_relu) {
                v0 = fmaxf(v0, 0.f); v1 = fmaxf(v1, 0.f);
                v2 = fmaxf(v2, 0.f); v3 = fmaxf(v3, 0.f);
            }
            if (r0 < nrows)
                *(float2*)&C[(size_t)r0 * mcols + ccol] = make_float2(v0, v1);
            if (r0 + 8 < nrows)
                *(float2*)&C[(size_t)(r0 + 8) * mcols + ccol] = make_float2(v2, v3);
        }
    }
}

// ---------------- pass 1 over edges: max distance + dst histogram -----------
__global__ void k_distmax_hist(const int* __restrict__ ei, const float* __restrict__ pos)
{
    int i = blockIdx.x * blockDim.x + threadIdx.x;
    float m = 0.f;
    for (; i < NEDGES; i += gridDim.x * blockDim.x) {
        int s = ei[i], d = ei[NEDGES + i];
        float ax = pos[3 * s + 0] - pos[3 * d + 0];
        float ay = pos[3 * s + 1] - pos[3 * d + 1];
        float az = pos[3 * s + 2] - pos[3 * d + 2];
        m = fmaxf(m, sqrtf(ax * ax + ay * ay + az * az));
        atomicAdd(&g_cnt[d], 1);
    }
#pragma unroll
    for (int o = 16; o; o >>= 1) m = fmaxf(m, __shfl_xor_sync(0xffffffffu, m, o));
    if ((threadIdx.x & 31) == 0) atomicMax(&g_distmax_bits, __float_as_uint(m));
}

// ---------------- exclusive scan of g_cnt -> g_off, g_cur (one block) -------
__global__ void __launch_bounds__(1024) k_scan()
{
    const int CH = (NNODES + 1023) / 1024;   // 49
    __shared__ int wsum[32];
    int t = threadIdx.x;
    int lane = t & 31, wid = t >> 5;
    int base = t * CH;

    int s = 0;
#pragma unroll 4
    for (int i = 0; i < CH; i++) {
        int idx = base + i;
        if (idx < NNODES) s += g_cnt[idx];
    }
    // inclusive warp scan
    int incl = s;
#pragma unroll
    for (int o = 1; o < 32; o <<= 1) {
        int v = __shfl_up_sync(0xffffffffu, incl, o);
        if (lane >= o) incl += v;
    }
    if (lane == 31) wsum[wid] = incl;
    __syncthreads();
    if (wid == 0) {
        int w = (lane < 32) ? wsum[lane] : 0;
        int wi = w;
#pragma unroll
        for (int o = 1; o < 32; o <<= 1) {
            int v = __shfl_up_sync(0xffffffffu, wi, o);
            if (lane >= o) wi += v;
        }
        wsum[lane] = wi - w;   // exclusive warp offsets
    }
    __syncthreads();
    int excl = wsum[wid] + incl - s;   // exclusive prefix for this thread
    int run = excl;
    for (int i = 0; i < CH; i++) {
        int idx = base + i;
        if (idx < NNODES) {
            g_off[idx] = run;
            g_cur[idx] = run;
            run += g_cnt[idx];
        }
    }
    if (t == 1023) g_off[NNODES] = NEDGES;
}

// ---------------- pass 2: compute ab[4] per edge, place into CSR order ------
__global__ void k_reorder(const int* __restrict__ ei, const float* __restrict__ pos,
                          const float* __restrict__ vfp, const float* __restrict__ vparams)
{
    int e = blockIdx.x * blockDim.x + threadIdx.x;
    if (e >= NEDGES) return;
    int s = __ldg(&ei[e]);
    int d = __ldg(&ei[NEDGES + e]);

    float ax = pos[3 * s + 0] - pos[3 * d + 0];
    float ay = pos[3 * s + 1] - pos[3 * d + 1];
    float az = pos[3 * s + 2] - pos[3 * d + 2];
    float dist = sqrtf(ax * ax + ay * ay + az * az);
    float dmax = __uint_as_float(g_distmax_bits);
    float r    = dist / dmax;
    float inv  = 1.f / (dist + 1e-8f);
    float dsum = (ax + ay + az) * inv;
    float vf   = vfp[0];

    float4 ab;
    {
        float v, g2;
        v = vf * fminf(r, vparams[0]); g2 = 1.f - v * v + 1e-8f;
        ab.x = sqrtf(g2) / (1.f + v * dsum);
        v = vf * fminf(r, vparams[1]); g2 = 1.f - v * v + 1e-8f;
        ab.y = sqrtf(g2) / (1.f + v * dsum);
        v = vf * fminf(r, vparams[2]); g2 = 1.f - v * v + 1e-8f;
        ab.z = sqrtf(g2) / (1.f + v * dsum);
        v = vf * fminf(r, vparams[3]); g2 = 1.f - v * v + 1e-8f;
        ab.w = sqrtf(g2) / (1.f + v * dsum);
    }
    int p = atomicAdd(&g_cur[d], 1);
    g_esrc[p] = s;
    g_eab[p]  = ab;
}

// ---------------- aggregate: one warp per node; fused BN column stats -------
__global__ void __launch_bounds__(256)
k_agg()
{
    const int lane = threadIdx.x & 31;
    const int wid  = (blockIdx.x << 3) + (threadIdx.x >> 5);
    const int nwarps = gridDim.x << 3;

    float csum[16], csq[16];
#pragma unroll
    for (int i = 0; i < 16; i++) { csum[i] = 0.f; csq[i] = 0.f; }

    for (int node = wid; node < NNODES; node += nwarps) {
        float4 acc0 = make_float4(0.f, 0.f, 0.f, 0.f);
        float4 acc1 = acc0, acc2 = acc0, acc3 = acc0;
        int p0 = g_off[node], p1 = g_off[node + 1];
        for (int p = p0; p < p1; p++) {
            int s = g_esrc[p];
            float4 ab = g_eab[p];
            float4 hv = *(const float4*)&g_hw[(size_t)s * HDIM + lane * 4];
            acc0.x = fmaf(ab.x, hv.x, acc0.x); acc0.y = fmaf(ab.x, hv.y, acc0.y);
            acc0.z = fmaf(ab.x, hv.z, acc0.z); acc0.w = fmaf(ab.x, hv.w, acc0.w);
            acc1.x = fmaf(ab.y, hv.x, acc1.x); acc1.y = fmaf(ab.y, hv.y, acc1.y);
            acc1.z = fmaf(ab.y, hv.z, acc1.z); acc1.w = fmaf(ab.y, hv.w, acc1.w);
            acc2.x = fmaf(ab.z, hv.x, acc2.x); acc2.y = fmaf(ab.z, hv.y, acc2.y);
            acc2.z = fmaf(ab.z, hv.z, acc2.z); acc2.w = fmaf(ab.z, hv.w, acc2.w);
            acc3.x = fmaf(ab.w, hv.x, acc3.x); acc3.y = fmaf(ab.w, hv.y, acc3.y);
            acc3.z = fmaf(ab.w, hv.z, acc3.z); acc3.w = fmaf(ab.w, hv.w, acc3.w);
        }
        float* op = &g_agg[(size_t)node * ZDIM + lane * 4];
        *(float4*)(op + 0 * HDIM) = acc0;
        *(float4*)(op + 1 * HDIM) = acc1;
        *(float4*)(op + 2 * HDIM) = acc2;
        *(float4*)(op + 3 * HDIM) = acc3;
        const float* a = (const float*)&acc0;
#pragma unroll
        for (int i = 0; i < 4; i++) { csum[i] += a[i]; csq[i] += a[i] * a[i]; }
        a = (const float*)&acc1;
#pragma unroll
        for (int i = 0; i < 4; i++) { csum[4 + i] += a[i]; csq[4 + i] += a[i] * a[i]; }
        a = (const float*)&acc2;
#pragma unroll
        for (int i = 0; i < 4; i++) { csum[8 + i] += a[i]; csq[8 + i] += a[i] * a[i]; }
        a = (const float*)&acc3;
#pragma unroll
        for (int i = 0; i < 4; i++) { csum[12 + i] += a[i]; csq[12 + i] += a[i] * a[i]; }
    }
    // column ids: k*128 + lane*4 + j  for k in 0..3, j in 0..3
#pragma unroll
    for (int k = 0; k < 4; k++)
#pragma unroll
        for (int j = 0; j < 4; j++) {
            int col = k * HDIM + lane * 4 + j;
            atomicAdd(&g_colsum[col],   (double)csum[k * 4 + j]);
            atomicAdd(&g_colsumsq[col], (double)csq[k * 4 + j]);
        }
}

__global__ void k_bnfinal(const float* __restrict__ bn_gamma,
                          const float* __restrict__ bn_beta,
                          const float* __restrict__ att)
{
    int c = blockIdx.x * blockDim.x + threadIdx.x;
    if (c >= ZDIM) return;
    float mean = (float)(g_colsum[c] * (1.0 / NNODES));
    float var  = (float)(g_colsumsq[c] * (1.0 / NNODES)) - mean * mean;
    float invs = 1.f / sqrtf(var + 1e-5f);
    float a  = att[c];                      // attention >= 0: fold through relu
    float sc = invs * bn_gamma[c];
    g_scale[c] = sc * a;
    g_shift[c] = (bn_beta[c] - mean * sc) * a;
}

// ---------------- LayerNorm (per row of z1 [N,256]) + relu, in place --------
__global__ void k_lnrelu(const float* __restrict__ gam, const float* __restrict__ bet)
{
    int row = blockIdx.x * (blockDim.x >> 5) + (threadIdx.x >> 5);
    if (row >= NNODES) return;
    int lane = threadIdx.x & 31;
    float* p = g_z1 + (size_t)row * MID;
    float v[8];
    float s = 0.f;
#pragma unroll
    for (int i = 0; i < 8; i++) { v[i] = p[lane + 32 * i]; s += v[i]; }
#pragma unroll
    for (int o = 16; o; o >>= 1) s += __shfl_xor_sync(0xffffffffu, s, o);
    float mean = s * (1.f / MID);
    float q = 0.f;
#pragma unroll
    for (int i = 0; i < 8; i++) { float t = v[i] - mean; q += t * t; }
#pragma unroll
    for (int o = 16; o; o >>= 1) q += __shfl_xor_sync(0xffffffffu, q, o);
    float inv = rsqrtf(q * (1.f / MID) + 1e-5f);
#pragma unroll
    for (int i = 0; i < 8; i++) {
        int c = lane + 32 * i;
        p[c] = fmaxf((v[i] - mean) * inv * gam[c] + bet[c], 0.f);
    }
}

// ---------------- launch -----------------------------------------------------
extern "C" void kernel_launch(void* const* d_in, const int* in_sizes, int n_in,
                              void* d_out, int out_size)
{
    const float* x        = (const float*)d_in[0];
    const int*   ei       = (const int*)  d_in[1];
    const float* pos      = (const float*)d_in[2];
    const float* W_ft     = (const float*)d_in[3];
    const float* b_ft     = (const float*)d_in[4];
    const float* W_conv   = (const float*)d_in[5];
    const float* b_conv   = (const float*)d_in[6];
    const float* vf       = (const float*)d_in[7];
    const float* vparams  = (const float*)d_in[8];
    const float* bn_gamma = (const float*)d_in[9];
    const float* bn_beta  = (const float*)d_in[10];
    const float* att      = (const float*)d_in[11];
    const float* W1       = (const float*)d_in[12];
    const float* b1       = (const float*)d_in[13];
    const float* ln_g     = (const float*)d_in[14];
    const float* ln_b     = (const float*)d_in[15];
    const float* W2       = (const float*)d_in[16];
    const float* b2       = (const float*)d_in[17];
    float* out = (float*)d_out;

    float *ph, *phw, *pagg, *pz1;
    cudaGetSymbolAddress((void**)&ph,   g_h);
    cudaGetSymbolAddress((void**)&phw,  g_hw);
    cudaGetSymbolAddress((void**)&pagg, g_agg);
    cudaGetSymbolAddress((void**)&pz1,  g_z1);

    const int ROWB = (NNODES + 127) / 128;  // 391

    // init counters
    k_zero_misc<<<64, 1024>>>();

    // feature transform + conv linear (applied per node; gather commutes)
    k_gemm_tf32<<<dim3(1, ROWB), 256>>>(x,  W_ft,   b_ft,   ph,  NNODES, FDIM, HDIM, 1, 0);
    k_gemm_tf32<<<dim3(1, ROWB), 256>>>(ph, W_conv, b_conv, phw, NNODES, HDIM, HDIM, 0, 0);

    // edge pass 1: max distance + dst histogram
    k_distmax_hist<<<1024, 256>>>(ei, pos);
    // CSR offsets
    k_scan<<<1, 1024>>>();
    // edge pass 2: per-edge ab factors into CSR slots
    k_reorder<<<(NEDGES + 255) / 256, 256>>>(ei, pos, vf, vparams);
    // gather-aggregate per node + fused BN column stats
    k_agg<<<1568, 256>>>();

    k_bnfinal<<<2, 256>>>(bn_gamma, bn_beta, att);

    // MLP head: relu(BN(agg))*att @ W1^T -> LN -> relu -> @ W2^T
    k_gemm_tf32<<<dim3(MID / 128, ROWB), 256>>>(pagg, W1, b1, pz1, NNODES, ZDIM, MID, 0, 1);
    k_lnrelu<<<(NNODES + 7) / 8, 256>>>(ln_g, ln_b);
    k_gemm_tf32<<<dim3(ODIM / 128, ROWB), 256>>>(pz1, W2, b2, out, NNODES, MID, ODIM, 0, 0);
}